// round 9
// baseline (speedup 1.0000x reference)
#include <cuda_runtime.h>
#include <cuda_bf16.h>
#include <mma.h>
#include <cstdint>
#include <cstdio>

using namespace nvcuda;

// ---------------- problem-fixed constants ----------------
#define DD 128
#define MAXN 32000
#define MAXE 290000

// ---------------- scratch (static device globals; no allocs allowed) ----------------
__device__ __align__(16) float g_y   [MAXN * DD];
__device__ __align__(16) float g_ai  [MAXN * DD];
__device__ __align__(16) float g_aj  [MAXN * DD];
__device__ __align__(16) float g_feat[MAXN * DD];
__device__ __align__(16) float g_h   [64 * DD];
__device__ __align__(16) float g_praw[MAXN];
__device__ int g_cnt   [MAXN];
__device__ int g_rowptr[MAXN + 1];
__device__ int g_cursor[MAXN];
__device__ int g_srcs  [MAXE];
__device__ int g_aux   [256];
// bf16 hi/lo weight images, row-major [n][k] (k contiguous)
__device__ __align__(16) __nv_bfloat16 g_wlinH[128 * 128];
__device__ __align__(16) __nv_bfloat16 g_wlinL[128 * 128];
__device__ __align__(16) __nv_bfloat16 g_watH [256 * 128];
__device__ __align__(16) __nv_bfloat16 g_watL [256 * 128];

// ---------------- weight prep: fp32 -> bf16 hi/lo (row-major) ----------------
__global__ void prep_w_kernel(const float* __restrict__ Wlin, const float* __restrict__ Wat,
                              __nv_bfloat16* __restrict__ linH, __nv_bfloat16* __restrict__ linL,
                              __nv_bfloat16* __restrict__ atH,  __nv_bfloat16* __restrict__ atL)
{
    int i = blockIdx.x * blockDim.x + threadIdx.x;
    if (i >= 16384 + 32768) return;
    float v;
    __nv_bfloat16 *dh, *dl;
    int o;
    if (i < 16384) {
        int n = i >> 7, k = i & 127;
        v = Wlin[n * 128 + k];
        dh = linH; dl = linL; o = i;
    } else {
        int j = i - 16384;
        int n = j >> 7, k = j & 127;
        v = (n < 128) ? Wat[n * 256 + k] : Wat[(n - 128) * 256 + 128 + k];
        dh = atH; dl = atL; o = j;
    }
    __nv_bfloat16 h = __float2bfloat16(v);
    __nv_bfloat16 l = __float2bfloat16(v - __bfloat162float(h));
    dh[o] = h;
    dl[o] = l;
}

// ---------------- wmma GEMM: C[M x N_out] = A[M x 128] @ W[N_out x 128]^T (+bias on cols<128) ----------------
// bf16 hi/lo 3-product split, fp32 accumulate. Block: 256 threads (8 warps), M-tile 64.
// Warp (wid) handles m-tile (wid&3)*16 and n-range (wid>>2)*(NTILES*16), NTILES 16-col tiles.
// NTILES=4 -> N_out=128 (all cols to C0, bias0). NTILES=8 -> N_out=256 (cols 0-127 -> C0 +bias, 128-255 -> C1).
template <int NTILES>
__global__ __launch_bounds__(256) void gemm_wmma_kernel(
    const float* __restrict__ A,
    const __nv_bfloat16* __restrict__ WH, const __nv_bfloat16* __restrict__ WL,
    const float* __restrict__ bias0,
    float* __restrict__ C0, float* __restrict__ C1, int M)
{
    constexpr int N_OUT = NTILES * 32;
    extern __shared__ char smc[];
    __nv_bfloat16* Ahi = reinterpret_cast<__nv_bfloat16*>(smc);
    __nv_bfloat16* Alo = Ahi + 64 * 128;
    __nv_bfloat16* Wh  = Alo + 64 * 128;
    __nv_bfloat16* Wl  = Wh + N_OUT * 128;
    float* biasRep     = reinterpret_cast<float*>(Wl + N_OUT * 128);   // [16][N_OUT]

    const int tid = threadIdx.x;
    const int wid = tid >> 5;
    const int m0 = blockIdx.x * 64;

    // stage W (linear uint4 copy of the pre-split images)
    {
        const uint4* sH = reinterpret_cast<const uint4*>(WH);
        const uint4* sL = reinterpret_cast<const uint4*>(WL);
        uint4* dH = reinterpret_cast<uint4*>(Wh);
        uint4* dL = reinterpret_cast<uint4*>(Wl);
        const int cnt = N_OUT * 16;   // (N_OUT*128*2 bytes)/16
        for (int i = tid; i < cnt; i += 256) { dH[i] = sH[i]; dL[i] = sL[i]; }
    }
    // stage A: fp32 -> bf16 hi/lo
    for (int idx = tid; idx < 64 * 32; idx += 256) {
        int row = idx >> 5, k = (idx & 31) << 2;
        int m = m0 + row;
        float4 v = make_float4(0.f, 0.f, 0.f, 0.f);
        if (m < M) v = *reinterpret_cast<const float4*>(A + (size_t)m * 128 + k);
        __nv_bfloat16 h0 = __float2bfloat16(v.x), h1 = __float2bfloat16(v.y);
        __nv_bfloat16 h2 = __float2bfloat16(v.z), h3 = __float2bfloat16(v.w);
        __nv_bfloat16 l0 = __float2bfloat16(v.x - __bfloat162float(h0));
        __nv_bfloat16 l1 = __float2bfloat16(v.y - __bfloat162float(h1));
        __nv_bfloat16 l2 = __float2bfloat16(v.z - __bfloat162float(h2));
        __nv_bfloat16 l3 = __float2bfloat16(v.w - __bfloat162float(h3));
        uint32_t hA = ((uint32_t)__bfloat16_as_ushort(h1) << 16) | __bfloat16_as_ushort(h0);
        uint32_t hB = ((uint32_t)__bfloat16_as_ushort(h3) << 16) | __bfloat16_as_ushort(h2);
        uint32_t lA = ((uint32_t)__bfloat16_as_ushort(l1) << 16) | __bfloat16_as_ushort(l0);
        uint32_t lB = ((uint32_t)__bfloat16_as_ushort(l3) << 16) | __bfloat16_as_ushort(l2);
        *reinterpret_cast<uint2*>(Ahi + row * 128 + k) = make_uint2(hA, hB);
        *reinterpret_cast<uint2*>(Alo + row * 128 + k) = make_uint2(lA, lB);
    }
    // stage bias-replicated tile [16][N_OUT] (cols >= 128 get 0)
    for (int idx = tid; idx < 16 * N_OUT; idx += 256) {
        int c = idx % N_OUT;
        biasRep[idx] = (c < 128) ? bias0[c] : 0.f;
    }
    __syncthreads();

    const int mrow = (wid & 3) * 16;
    const int nbase = (wid >> 2) * (NTILES * 16);

    wmma::fragment<wmma::accumulator, 16, 16, 16, float> acc[NTILES];
#pragma unroll
    for (int t = 0; t < NTILES; t++)
        wmma::load_matrix_sync(acc[t], biasRep + nbase + t * 16, N_OUT, wmma::mem_row_major);

#pragma unroll
    for (int s = 0; s < 8; s++) {
        const int k0 = s * 16;
        wmma::fragment<wmma::matrix_a, 16, 16, 16, __nv_bfloat16, wmma::row_major> aH, aL;
        wmma::load_matrix_sync(aH, Ahi + mrow * 128 + k0, 128);
        wmma::load_matrix_sync(aL, Alo + mrow * 128 + k0, 128);
#pragma unroll
        for (int t = 0; t < NTILES; t++) {
            const int n0 = nbase + t * 16;
            wmma::fragment<wmma::matrix_b, 16, 16, 16, __nv_bfloat16, wmma::col_major> bH, bL;
            wmma::load_matrix_sync(bH, Wh + n0 * 128 + k0, 128);
            wmma::load_matrix_sync(bL, Wl + n0 * 128 + k0, 128);
            wmma::mma_sync(acc[t], aH, bH, acc[t]);
            wmma::mma_sync(acc[t], aH, bL, acc[t]);
            wmma::mma_sync(acc[t], aL, bH, acc[t]);
        }
    }

    const int m = m0 + mrow;
    if (m0 + 64 <= M) {
        // full tile: direct store
#pragma unroll
        for (int t = 0; t < NTILES; t++) {
            const int n0 = nbase + t * 16;
            float* dst = (n0 < 128) ? (C0 + (size_t)m * 128 + n0)
                                    : (C1 + (size_t)m * 128 + (n0 - 128));
            wmma::store_matrix_sync(dst, acc[t], 128, wmma::mem_row_major);
        }
    } else {
        // partial tail: stage through per-warp scratch (reuse biasRep)
        __syncthreads();
        float* scr = biasRep + wid * 256;
        const int lane = tid & 31;
#pragma unroll
        for (int t = 0; t < NTILES; t++) {
            wmma::store_matrix_sync(scr, acc[t], 16, wmma::mem_row_major);
            __syncwarp();
            const int n0 = nbase + t * 16;
            for (int e = lane; e < 256; e += 32) {
                int r = e >> 4, c = e & 15;
                int mm = m + r;
                if (mm < M) {
                    float* dst = (n0 < 128) ? (C0 + (size_t)mm * 128 + n0 + c)
                                            : (C1 + (size_t)mm * 128 + (n0 - 128) + c);
                    *dst = scr[r * 16 + c];
                }
            }
            __syncwarp();
        }
    }
}

// ---------------- CSR build ----------------
__global__ void zero_kernel(int* __restrict__ p, int N) {
    int i = blockIdx.x * blockDim.x + threadIdx.x;
    if (i < N) p[i] = 0;
}

__global__ void hist_kernel(const int* __restrict__ dst, int E, int N, int* __restrict__ cnt) {
    int i = blockIdx.x * blockDim.x + threadIdx.x;
    if (i < E + N) {
        int d = (i < E) ? dst[i] : (i - E);
        atomicAdd(cnt + d, 1);
    }
}

__device__ __forceinline__ int block_incl_scan256(int v, int tid) {
    __shared__ int ws[8];
    int lane = tid & 31, wid = tid >> 5;
#pragma unroll
    for (int off = 1; off < 32; off <<= 1) {
        int t = __shfl_up_sync(0xffffffffu, v, off);
        if (lane >= off) v += t;
    }
    if (lane == 31) ws[wid] = v;
    __syncthreads();
    if (wid == 0) {
        int s = (lane < 8) ? ws[lane] : 0;
#pragma unroll
        for (int off = 1; off < 8; off <<= 1) {
            int t = __shfl_up_sync(0xffffffffu, s, off);
            if (lane >= off) s += t;
        }
        if (lane < 8) ws[lane] = s;
    }
    __syncthreads();
    if (wid > 0) v += ws[wid - 1];
    return v;
}

__global__ void scan1_kernel(const int* __restrict__ cnt, int N, int* __restrict__ rowptr, int* __restrict__ aux) {
    int t = threadIdx.x;
    int gid = blockIdx.x * 256 + t;
    int c = (gid < N) ? cnt[gid] : 0;
    int incl = block_incl_scan256(c, t);
    if (gid < N) rowptr[gid] = incl - c;
    if (t == 255) aux[blockIdx.x] = incl;
}

__global__ void scan2_kernel(int* __restrict__ aux, int nb, int N, int Etot, int* __restrict__ rowptr) {
    int t = threadIdx.x;
    int v0 = (t < nb) ? aux[t] : 0;
    int incl = block_incl_scan256(v0, t);
    if (t < nb) aux[t] = incl - v0;
    if (t == 0) rowptr[N] = Etot;
}

__global__ void scan3_kernel(int* __restrict__ rowptr, const int* __restrict__ aux,
                             int* __restrict__ cursor, int N) {
    int gid = blockIdx.x * blockDim.x + threadIdx.x;
    if (gid < N) {
        int v = rowptr[gid] + aux[blockIdx.x];
        rowptr[gid] = v;
        cursor[gid] = v;
    }
}

__global__ void scatter_kernel(const int* __restrict__ src, const int* __restrict__ dst,
                               int E, int N, int* __restrict__ cursor, int* __restrict__ out) {
    int i = blockIdx.x * blockDim.x + threadIdx.x;
    if (i < E + N) {
        int s, d;
        if (i < E) { s = src[i]; d = dst[i]; }
        else       { s = i - E; d = i - E; }
        int pos = atomicAdd(cursor + d, 1);
        out[pos] = s;
    }
}

// ---------------- GAT edge softmax + aggregate (one warp per dst node, float4 lanes) ----------------
__global__ void edge_agg_kernel(const int* __restrict__ rowptr, const int* __restrict__ srcs,
                                const float* __restrict__ ai, const float* __restrict__ aj,
                                const float* __restrict__ y, float* __restrict__ out, int N)
{
    int w = (blockIdx.x * blockDim.x + threadIdx.x) >> 5;
    int lane = threadIdx.x & 31;
    if (w >= N) return;
    const int c = lane * 4;
    float4 ai4 = *reinterpret_cast<const float4*>(ai + (size_t)w * 128 + c);
    float4 den = make_float4(0.f, 0.f, 0.f, 0.f);
    float4 num = make_float4(0.f, 0.f, 0.f, 0.f);
    int e0 = rowptr[w], e1 = rowptr[w + 1];
    int s_next = (e0 < e1) ? srcs[e0] : 0;
    for (int j = e0; j < e1; j++) {
        int s = s_next;
        if (j + 1 < e1) s_next = srcs[j + 1];
        float4 aj4 = *reinterpret_cast<const float4*>(aj + (size_t)s * 128 + c);
        float4 y4  = *reinterpret_cast<const float4*>(y  + (size_t)s * 128 + c);
        float a, e;
        a = ai4.x + aj4.x; a = fmaxf(a, 0.2f * a); e = __expf(a); den.x += e; num.x += e * y4.x;
        a = ai4.y + aj4.y; a = fmaxf(a, 0.2f * a); e = __expf(a); den.y += e; num.y += e * y4.y;
        a = ai4.z + aj4.z; a = fmaxf(a, 0.2f * a); e = __expf(a); den.z += e; num.z += e * y4.z;
        a = ai4.w + aj4.w; a = fmaxf(a, 0.2f * a); e = __expf(a); den.w += e; num.w += e * y4.w;
    }
    float4 o;
    o.x = num.x / (den.x + 1e-16f);
    o.y = num.y / (den.y + 1e-16f);
    o.z = num.z / (den.z + 1e-16f);
    o.w = num.w / (den.w + 1e-16f);
    *reinterpret_cast<float4*>(out + (size_t)w * 128 + c) = o;
}

// ---------------- GRU ----------------
__global__ void gru_kernel(const float* __restrict__ state, const float* __restrict__ input_,
                           const float* __restrict__ W_in, const float* __restrict__ W_z,
                           const float* __restrict__ W_r, const float* __restrict__ W_h,
                           float* __restrict__ h_out, float* __restrict__ h_out2, int L)
{
    __shared__ float mi[128], inp[128], st[128], rs[128], zz[128];
    int b = blockIdx.x, t = threadIdx.x;
    const float* ib = input_ + (size_t)b * L * 128;
    float s = 0.f;
    for (int l = 0; l < L; l++) s += ib[l * 128 + t];
    mi[t] = s / (float)L;
    st[t] = state[b * 128 + t];
    __syncthreads();
    {
        float acc = 0.f;
        const float* wr = W_in + t * 128;
        for (int d = 0; d < 128; d++) acc += mi[d] * wr[d];
        inp[t] = acc;
    }
    __syncthreads();
    float az = 0.f, ar = 0.f;
    {
        const float* wz = W_z + t * 256;
        const float* wr = W_r + t * 256;
        for (int d = 0; d < 128; d++) { az += st[d] * wz[d];        ar += st[d] * wr[d]; }
        for (int d = 0; d < 128; d++) { az += inp[d] * wz[128 + d]; ar += inp[d] * wr[128 + d]; }
    }
    float z = 1.f / (1.f + expf(-az));
    float r = 1.f / (1.f + expf(-ar));
    zz[t] = z;
    rs[t] = r * st[t];
    __syncthreads();
    float ah = 0.f;
    {
        const float* wh = W_h + t * 256;
        for (int d = 0; d < 128; d++) ah += rs[d] * wh[d];
        for (int d = 0; d < 128; d++) ah += inp[d] * wh[128 + d];
    }
    float ht = tanhf(ah);
    float h = (1.f - zz[t]) * st[t] + zz[t] * ht;
    h_out[b * 128 + t] = h;
    h_out2[b * 128 + t] = h;
}

// ---------------- head: prob logits + sisr (one warp per node, float4 lanes) ----------------
__global__ void head_kernel(const float* __restrict__ feat, const float* __restrict__ h,
                            const float* __restrict__ Wp, const float* __restrict__ bp,
                            const float* __restrict__ Wsv, const float* __restrict__ bsv,
                            float* __restrict__ praw, float* __restrict__ sisr, int N, int NN)
{
    int w = (blockIdx.x * blockDim.x + threadIdx.x) >> 5;
    int lane = threadIdx.x & 31;
    if (w >= N) return;
    int b = w / NN;
    const int c = lane * 4;
    float4 f  = *reinterpret_cast<const float4*>(feat + (size_t)w * 128 + c);
    float4 hh = *reinterpret_cast<const float4*>(h + b * 128 + c);
    float4 wp = *reinterpret_cast<const float4*>(Wp + c);
    float4 ws = *reinterpret_cast<const float4*>(Wsv + c);
    float4 xg;
    xg.x = f.x * hh.x; xg.y = f.y * hh.y; xg.z = f.z * hh.z; xg.w = f.w * hh.w;
    float p = xg.x * wp.x + xg.y * wp.y + xg.z * wp.z + xg.w * wp.w;
    float s = xg.x * ws.x + xg.y * ws.y + xg.z * ws.z + xg.w * ws.w;
    for (int off = 16; off; off >>= 1) {
        p += __shfl_xor_sync(0xffffffffu, p, off);
        s += __shfl_xor_sync(0xffffffffu, s, off);
    }
    if (lane == 0) {
        praw[w] = p + bp[0];
        sisr[w] = 1.f / (1.f + expf(-(s + bsv[0])));
    }
}

// ---------------- softmax over prob[:, 1:] per batch ----------------
__global__ void softmax_kernel(const float* __restrict__ praw, float* __restrict__ prob, int NN)
{
    __shared__ float red[512];
    int b = blockIdx.x, t = threadIdx.x;
    int n = t + 1;
    float v = (n < NN) ? praw[b * NN + n] : -1e30f;
    red[t] = v; __syncthreads();
    for (int off = 256; off; off >>= 1) {
        if (t < off) red[t] = fmaxf(red[t], red[t + off]);
        __syncthreads();
    }
    float m = red[0];
    __syncthreads();
    float e = (n < NN) ? expf(v - m) : 0.f;
    red[t] = e; __syncthreads();
    for (int off = 256; off; off >>= 1) {
        if (t < off) red[t] = red[t] + red[t + off];
        __syncthreads();
    }
    float sum = red[0];
    if (n < NN) prob[b * (NN - 1) + t] = e / sum;
}

// ---------------- launch ----------------
extern "C" void kernel_launch(void* const* d_in, const int* in_sizes, int n_in,
                              void* d_out, int out_size)
{
    const float* x      = (const float*)d_in[0];
    const int*   e0     = (const int*)  d_in[1];
    const int*   e1     = (const int*)  d_in[2];
    const float* state  = (const float*)d_in[3];
    const float* input_ = (const float*)d_in[4];
    const float* W_in   = (const float*)d_in[5];
    const float* W_z    = (const float*)d_in[6];
    const float* W_r    = (const float*)d_in[7];
    const float* W_h    = (const float*)d_in[8];
    const float* Wlin[2] = { (const float*)d_in[9],  (const float*)d_in[13] };
    const float* blin[2] = { (const float*)d_in[10], (const float*)d_in[14] };
    const float* Wat [2] = { (const float*)d_in[11], (const float*)d_in[15] };
    const float* bat [2] = { (const float*)d_in[12], (const float*)d_in[16] };
    const float* Wp     = (const float*)d_in[17];
    const float* bp     = (const float*)d_in[18];
    const float* Wsv    = (const float*)d_in[19];
    const float* bsv    = (const float*)d_in[20];

    const int N    = in_sizes[0] / 128;
    const int E    = in_sizes[1] / 2;
    const int B    = in_sizes[3] / 128;
    const int L    = in_sizes[4] / (B * 128);
    const int NN   = N / B;
    const int Etot = E + N;

    float *yp, *aip, *ajp, *featp, *hp, *prawp;
    int *cntp, *rowp, *curp, *srcp, *auxp;
    __nv_bfloat16 *wlinH, *wlinL, *watH, *watL;
    cudaGetSymbolAddress((void**)&yp,    g_y);
    cudaGetSymbolAddress((void**)&aip,   g_ai);
    cudaGetSymbolAddress((void**)&ajp,   g_aj);
    cudaGetSymbolAddress((void**)&featp, g_feat);
    cudaGetSymbolAddress((void**)&hp,    g_h);
    cudaGetSymbolAddress((void**)&prawp, g_praw);
    cudaGetSymbolAddress((void**)&cntp,  g_cnt);
    cudaGetSymbolAddress((void**)&rowp,  g_rowptr);
    cudaGetSymbolAddress((void**)&curp,  g_cursor);
    cudaGetSymbolAddress((void**)&srcp,  g_srcs);
    cudaGetSymbolAddress((void**)&auxp,  g_aux);
    cudaGetSymbolAddress((void**)&wlinH, g_wlinH);
    cudaGetSymbolAddress((void**)&wlinL, g_wlinL);
    cudaGetSymbolAddress((void**)&watH,  g_watH);
    cudaGetSymbolAddress((void**)&watL,  g_watL);

    float* out      = (float*)d_out;
    float* out_prob = out;
    float* out_sisr = out + (size_t)B * (NN - 1);
    float* out_h    = out + (size_t)B * (NN - 1) + (size_t)B * NN;

    // dynamic smem: A(32KB) + W(N*512B) + biasRep(16*N*4B)
    const int smN128 = 64 * 128 * 4 + 128 * 128 * 4 + 16 * 128 * 4;   // 32768+65536+8192  = 106496
    const int smN256 = 64 * 128 * 4 + 256 * 128 * 4 + 16 * 256 * 4;   // 32768+131072+16384 = 180224
    cudaFuncSetAttribute(gemm_wmma_kernel<4>, cudaFuncAttributeMaxDynamicSharedMemorySize, smN128);
    cudaFuncSetAttribute(gemm_wmma_kernel<8>, cudaFuncAttributeMaxDynamicSharedMemorySize, smN256);

    const int nbScan = (N + 255) / 256;
    const int gHist  = (Etot + 255) / 256;
    const int gWarp  = (N * 32 + 255) / 256;
    const int gTc    = (N + 63) / 64;

    gru_kernel<<<B, 128>>>(state, input_, W_in, W_z, W_r, W_h, hp, out_h, L);           // 1

    for (int layer = 0; layer < 2; layer++) {
        const int* ei = layer ? e1 : e0;           // [2, E]: row 0 = src, row 1 = dst
        const float* Ain = layer ? featp : x;

        prep_w_kernel<<<192, 256>>>(Wlin[layer], Wat[layer], wlinH, wlinL, watH, watL); // 2
        zero_kernel  <<<nbScan, 256>>>(cntp, N);                                        // 3

        // y = A@Wlin^T + blin   (4th launch overall -> ncu capture slot)
        gemm_wmma_kernel<4><<<gTc, 256, smN128>>>(Ain, wlinH, wlinL, blin[layer],
                                                  yp, yp, N);                           // 4

        hist_kernel   <<<gHist, 256>>>(ei + E, E, N, cntp);
        scan1_kernel  <<<nbScan, 256>>>(cntp, N, rowp, auxp);
        scan2_kernel  <<<1, 256>>>(auxp, nbScan, N, Etot, rowp);
        scan3_kernel  <<<nbScan, 256>>>(rowp, auxp, curp, N);
        scatter_kernel<<<gHist, 256>>>(ei, ei + E, E, N, curp, srcp);

        // fused attention: cols 0-127 -> ai (+b_attn), cols 128-255 -> aj
        gemm_wmma_kernel<8><<<gTc, 256, smN256>>>(yp, watH, watL, bat[layer],
                                                  aip, ajp, N);

        edge_agg_kernel<<<gWarp, 256>>>(rowp, srcp, aip, ajp, yp, featp, N);
    }

    head_kernel   <<<gWarp, 256>>>(featp, hp, Wp, bp, Wsv, bsv, prawp, out_sisr, N, NN);
    softmax_kernel<<<B, 512>>>(prawp, out_prob, NN);
}

// round 12
// speedup vs baseline: 1.2748x; 1.2748x over previous
#include <cuda_runtime.h>
#include <cuda_bf16.h>
#include <mma.h>
#include <cstdint>
#include <cstdio>

using namespace nvcuda;

// ---------------- problem-fixed constants ----------------
#define DD 128
#define MAXN 32000
#define MAXE 290000

// ---------------- scratch (static device globals; no allocs allowed) ----------------
__device__ __align__(16) float g_y   [MAXN * DD];
__device__ __align__(16) float g_ai  [MAXN * DD];
__device__ __align__(16) float g_aj  [MAXN * DD];
__device__ __align__(16) float g_feat[MAXN * DD];
__device__ __align__(16) float g_h   [64 * DD];
__device__ __align__(16) float g_praw[MAXN];
__device__ int g_cnt   [MAXN];
__device__ int g_rowptr[MAXN + 1];
__device__ int g_cursor[MAXN];
__device__ int g_srcs  [MAXE];
__device__ int g_aux   [256];
// bf16 hi/lo weight images, row-major [n][k] (k contiguous)
__device__ __align__(16) __nv_bfloat16 g_wlinH[128 * 128];
__device__ __align__(16) __nv_bfloat16 g_wlinL[128 * 128];
__device__ __align__(16) __nv_bfloat16 g_watH [256 * 128];
__device__ __align__(16) __nv_bfloat16 g_watL [256 * 128];

// ---------------- weight prep: fp32 -> bf16 hi/lo (row-major) ----------------
__global__ void prep_w_kernel(const float* __restrict__ Wlin, const float* __restrict__ Wat,
                              __nv_bfloat16* __restrict__ linH, __nv_bfloat16* __restrict__ linL,
                              __nv_bfloat16* __restrict__ atH,  __nv_bfloat16* __restrict__ atL)
{
    int i = blockIdx.x * blockDim.x + threadIdx.x;
    if (i >= 16384 + 32768) return;
    float v;
    __nv_bfloat16 *dh, *dl;
    int o;
    if (i < 16384) {
        int n = i >> 7, k = i & 127;
        v = Wlin[n * 128 + k];
        dh = linH; dl = linL; o = i;
    } else {
        int j = i - 16384;
        int n = j >> 7, k = j & 127;
        v = (n < 128) ? Wat[n * 256 + k] : Wat[(n - 128) * 256 + 128 + k];
        dh = atH; dl = atL; o = j;
    }
    __nv_bfloat16 h = __float2bfloat16(v);
    __nv_bfloat16 l = __float2bfloat16(v - __bfloat162float(h));
    dh[o] = h;
    dl[o] = l;
}

// ---------------- wmma GEMM v3 ----------------
// C[M x N_OUT] = A[M x 128] @ W[N_OUT x 128]^T, bf16 hi/lo 3-product split, fp32 acc.
// Warp tile 32m x 64n (acc 2x4). B fragments loaded DIRECTLY from global weight
// image (L1-resident, shared across blocks). Only A (hi/lo) staged in smem.
// N_OUT=128: M_TILE=128 (warps: 4 m-pos x 2 n-pos), bias0 on all cols -> C0.
// N_OUT=256: M_TILE=64  (warps: 2 m-pos x 4 n-pos), cols<128 -> C0 (+bias0), cols>=128 -> C1.
template <int N_OUT>
__global__ __launch_bounds__(256) void gemm_wmma_kernel(
    const float* __restrict__ A,
    const __nv_bfloat16* __restrict__ WH, const __nv_bfloat16* __restrict__ WL,
    const float* __restrict__ bias0,
    float* __restrict__ C0, float* __restrict__ C1, int M)
{
    constexpr int MPOS   = (N_OUT == 128) ? 4 : 2;
    constexpr int M_TILE = MPOS * 32;
    extern __shared__ char smc[];
    __nv_bfloat16* Ahi = reinterpret_cast<__nv_bfloat16*>(smc);
    __nv_bfloat16* Alo = Ahi + M_TILE * 128;
    float* biasRep     = reinterpret_cast<float*>(Alo + M_TILE * 128);   // [16][N_OUT]

    const int tid = threadIdx.x;
    const int wid = tid >> 5;
    const int m0 = blockIdx.x * M_TILE;

    // stage A: fp32 -> bf16 hi/lo (coalesced: warp spans one row's k)
    for (int idx = tid; idx < M_TILE * 32; idx += 256) {
        int row = idx >> 5, k = (idx & 31) << 2;
        int m = m0 + row;
        float4 v = make_float4(0.f, 0.f, 0.f, 0.f);
        if (m < M) v = *reinterpret_cast<const float4*>(A + (size_t)m * 128 + k);
        __nv_bfloat16 h0 = __float2bfloat16(v.x), h1 = __float2bfloat16(v.y);
        __nv_bfloat16 h2 = __float2bfloat16(v.z), h3 = __float2bfloat16(v.w);
        __nv_bfloat16 l0 = __float2bfloat16(v.x - __bfloat162float(h0));
        __nv_bfloat16 l1 = __float2bfloat16(v.y - __bfloat162float(h1));
        __nv_bfloat16 l2 = __float2bfloat16(v.z - __bfloat162float(h2));
        __nv_bfloat16 l3 = __float2bfloat16(v.w - __bfloat162float(h3));
        uint32_t hA = ((uint32_t)__bfloat16_as_ushort(h1) << 16) | __bfloat16_as_ushort(h0);
        uint32_t hB = ((uint32_t)__bfloat16_as_ushort(h3) << 16) | __bfloat16_as_ushort(h2);
        uint32_t lA = ((uint32_t)__bfloat16_as_ushort(l1) << 16) | __bfloat16_as_ushort(l0);
        uint32_t lB = ((uint32_t)__bfloat16_as_ushort(l3) << 16) | __bfloat16_as_ushort(l2);
        *reinterpret_cast<uint2*>(Ahi + row * 128 + k) = make_uint2(hA, hB);
        *reinterpret_cast<uint2*>(Alo + row * 128 + k) = make_uint2(lA, lB);
    }
    // stage bias-replicated tile [16][N_OUT] (cols >= 128 get 0)
    for (int idx = tid; idx < 16 * N_OUT; idx += 256) {
        int c = idx % N_OUT;
        biasRep[idx] = (c < 128) ? bias0[c] : 0.f;
    }
    __syncthreads();

    const int m_sub  = (wid % MPOS) * 32;     // warp's 32 m-rows within tile
    const int n_base = (wid / MPOS) * 64;     // warp's 64 n-cols

    wmma::fragment<wmma::accumulator, 16, 16, 16, float> acc[2][4];
#pragma unroll
    for (int i = 0; i < 2; i++)
#pragma unroll
        for (int t = 0; t < 4; t++)
            wmma::load_matrix_sync(acc[i][t], biasRep + n_base + t * 16, N_OUT, wmma::mem_row_major);

#pragma unroll
    for (int s = 0; s < 8; s++) {
        const int k0 = s * 16;
        wmma::fragment<wmma::matrix_a, 16, 16, 16, __nv_bfloat16, wmma::row_major> aH[2], aL[2];
#pragma unroll
        for (int i = 0; i < 2; i++) {
            wmma::load_matrix_sync(aH[i], Ahi + (m_sub + i * 16) * 128 + k0, 128);
            wmma::load_matrix_sync(aL[i], Alo + (m_sub + i * 16) * 128 + k0, 128);
        }
#pragma unroll
        for (int t = 0; t < 4; t++) {
            const int n0 = n_base + t * 16;
            wmma::fragment<wmma::matrix_b, 16, 16, 16, __nv_bfloat16, wmma::col_major> bH, bL;
            // direct global loads: W image row-major [n][k] == col-major B, ldm=128
            wmma::load_matrix_sync(bH, WH + (size_t)n0 * 128 + k0, 128);
            wmma::load_matrix_sync(bL, WL + (size_t)n0 * 128 + k0, 128);
#pragma unroll
            for (int i = 0; i < 2; i++) {
                wmma::mma_sync(acc[i][t], aH[i], bH, acc[i][t]);
                wmma::mma_sync(acc[i][t], aH[i], bL, acc[i][t]);
                wmma::mma_sync(acc[i][t], aL[i], bH, acc[i][t]);
            }
        }
    }

    if (m0 + M_TILE <= M) {
        // full tile: direct stores
#pragma unroll
        for (int i = 0; i < 2; i++) {
            const int m = m0 + m_sub + i * 16;
#pragma unroll
            for (int t = 0; t < 4; t++) {
                const int n0 = n_base + t * 16;
                float* dst = (n0 < 128) ? (C0 + (size_t)m * 128 + n0)
                                        : (C1 + (size_t)m * 128 + (n0 - 128));
                wmma::store_matrix_sync(dst, acc[i][t], 128, wmma::mem_row_major);
            }
        }
    } else {
        // tail: stage through per-warp scratch in the (now dead) A region
        __syncthreads();
        float* scr = reinterpret_cast<float*>(smc) + wid * 256;
        const int lane = tid & 31;
#pragma unroll
        for (int i = 0; i < 2; i++) {
            const int m = m0 + m_sub + i * 16;
#pragma unroll
            for (int t = 0; t < 4; t++) {
                const int n0 = n_base + t * 16;
                wmma::store_matrix_sync(scr, acc[i][t], 16, wmma::mem_row_major);
                __syncwarp();
                for (int e = lane; e < 256; e += 32) {
                    int r = e >> 4, c = e & 15;
                    int mm = m + r;
                    if (mm < M) {
                        float* dst = (n0 < 128) ? (C0 + (size_t)mm * 128 + n0 + c)
                                                : (C1 + (size_t)mm * 128 + (n0 - 128) + c);
                        *dst = scr[r * 16 + c];
                    }
                }
                __syncwarp();
            }
        }
    }
}

// ---------------- CSR build ----------------
__global__ void zero_kernel(int* __restrict__ p, int N) {
    int i = blockIdx.x * blockDim.x + threadIdx.x;
    if (i < N) p[i] = 0;
}

__global__ void hist_kernel(const int* __restrict__ dst, int E, int N, int* __restrict__ cnt) {
    int i = blockIdx.x * blockDim.x + threadIdx.x;
    if (i < E + N) {
        int d = (i < E) ? dst[i] : (i - E);
        atomicAdd(cnt + d, 1);
    }
}

__device__ __forceinline__ int block_incl_scan256(int v, int tid) {
    __shared__ int ws[8];
    int lane = tid & 31, wid = tid >> 5;
#pragma unroll
    for (int off = 1; off < 32; off <<= 1) {
        int t = __shfl_up_sync(0xffffffffu, v, off);
        if (lane >= off) v += t;
    }
    if (lane == 31) ws[wid] = v;
    __syncthreads();
    if (wid == 0) {
        int s = (lane < 8) ? ws[lane] : 0;
#pragma unroll
        for (int off = 1; off < 8; off <<= 1) {
            int t = __shfl_up_sync(0xffffffffu, s, off);
            if (lane >= off) s += t;
        }
        if (lane < 8) ws[lane] = s;
    }
    __syncthreads();
    if (wid > 0) v += ws[wid - 1];
    return v;
}

__global__ void scan1_kernel(const int* __restrict__ cnt, int N, int* __restrict__ rowptr, int* __restrict__ aux) {
    int t = threadIdx.x;
    int gid = blockIdx.x * 256 + t;
    int c = (gid < N) ? cnt[gid] : 0;
    int incl = block_incl_scan256(c, t);
    if (gid < N) rowptr[gid] = incl - c;
    if (t == 255) aux[blockIdx.x] = incl;
}

__global__ void scan2_kernel(int* __restrict__ aux, int nb, int N, int Etot, int* __restrict__ rowptr) {
    int t = threadIdx.x;
    int v0 = (t < nb) ? aux[t] : 0;
    int incl = block_incl_scan256(v0, t);
    if (t < nb) aux[t] = incl - v0;
    if (t == 0) rowptr[N] = Etot;
}

__global__ void scan3_kernel(int* __restrict__ rowptr, const int* __restrict__ aux,
                             int* __restrict__ cursor, int N) {
    int gid = blockIdx.x * blockDim.x + threadIdx.x;
    if (gid < N) {
        int v = rowptr[gid] + aux[blockIdx.x];
        rowptr[gid] = v;
        cursor[gid] = v;
    }
}

__global__ void scatter_kernel(const int* __restrict__ src, const int* __restrict__ dst,
                               int E, int N, int* __restrict__ cursor, int* __restrict__ out) {
    int i = blockIdx.x * blockDim.x + threadIdx.x;
    if (i < E + N) {
        int s, d;
        if (i < E) { s = src[i]; d = dst[i]; }
        else       { s = i - E; d = i - E; }
        int pos = atomicAdd(cursor + d, 1);
        out[pos] = s;
    }
}

// ---------------- GAT edge softmax + aggregate (one warp per dst node, float4 lanes) ----------------
__global__ void edge_agg_kernel(const int* __restrict__ rowptr, const int* __restrict__ srcs,
                                const float* __restrict__ ai, const float* __restrict__ aj,
                                const float* __restrict__ y, float* __restrict__ out, int N)
{
    int w = (blockIdx.x * blockDim.x + threadIdx.x) >> 5;
    int lane = threadIdx.x & 31;
    if (w >= N) return;
    const int c = lane * 4;
    float4 ai4 = *reinterpret_cast<const float4*>(ai + (size_t)w * 128 + c);
    float4 den = make_float4(0.f, 0.f, 0.f, 0.f);
    float4 num = make_float4(0.f, 0.f, 0.f, 0.f);
    int e0 = rowptr[w], e1 = rowptr[w + 1];
    int s_next = (e0 < e1) ? srcs[e0] : 0;
    for (int j = e0; j < e1; j++) {
        int s = s_next;
        if (j + 1 < e1) s_next = srcs[j + 1];
        float4 aj4 = *reinterpret_cast<const float4*>(aj + (size_t)s * 128 + c);
        float4 y4  = *reinterpret_cast<const float4*>(y  + (size_t)s * 128 + c);
        float a, e;
        a = ai4.x + aj4.x; a = fmaxf(a, 0.2f * a); e = __expf(a); den.x += e; num.x += e * y4.x;
        a = ai4.y + aj4.y; a = fmaxf(a, 0.2f * a); e = __expf(a); den.y += e; num.y += e * y4.y;
        a = ai4.z + aj4.z; a = fmaxf(a, 0.2f * a); e = __expf(a); den.z += e; num.z += e * y4.z;
        a = ai4.w + aj4.w; a = fmaxf(a, 0.2f * a); e = __expf(a); den.w += e; num.w += e * y4.w;
    }
    float4 o;
    o.x = num.x / (den.x + 1e-16f);
    o.y = num.y / (den.y + 1e-16f);
    o.z = num.z / (den.z + 1e-16f);
    o.w = num.w / (den.w + 1e-16f);
    *reinterpret_cast<float4*>(out + (size_t)w * 128 + c) = o;
}

// ---------------- GRU ----------------
__global__ void gru_kernel(const float* __restrict__ state, const float* __restrict__ input_,
                           const float* __restrict__ W_in, const float* __restrict__ W_z,
                           const float* __restrict__ W_r, const float* __restrict__ W_h,
                           float* __restrict__ h_out, float* __restrict__ h_out2, int L)
{
    __shared__ float mi[128], inp[128], st[128], rs[128], zz[128];
    int b = blockIdx.x, t = threadIdx.x;
    const float* ib = input_ + (size_t)b * L * 128;
    float s = 0.f;
    for (int l = 0; l < L; l++) s += ib[l * 128 + t];
    mi[t] = s / (float)L;
    st[t] = state[b * 128 + t];
    __syncthreads();
    {
        float acc = 0.f;
        const float* wr = W_in + t * 128;
        for (int d = 0; d < 128; d++) acc += mi[d] * wr[d];
        inp[t] = acc;
    }
    __syncthreads();
    float az = 0.f, ar = 0.f;
    {
        const float* wz = W_z + t * 256;
        const float* wr = W_r + t * 256;
        for (int d = 0; d < 128; d++) { az += st[d] * wz[d];        ar += st[d] * wr[d]; }
        for (int d = 0; d < 128; d++) { az += inp[d] * wz[128 + d]; ar += inp[d] * wr[128 + d]; }
    }
    float z = 1.f / (1.f + expf(-az));
    float r = 1.f / (1.f + expf(-ar));
    zz[t] = z;
    rs[t] = r * st[t];
    __syncthreads();
    float ah = 0.f;
    {
        const float* wh = W_h + t * 256;
        for (int d = 0; d < 128; d++) ah += rs[d] * wh[d];
        for (int d = 0; d < 128; d++) ah += inp[d] * wh[128 + d];
    }
    float ht = tanhf(ah);
    float h = (1.f - zz[t]) * st[t] + zz[t] * ht;
    h_out[b * 128 + t] = h;
    h_out2[b * 128 + t] = h;
}

// ---------------- head: prob logits + sisr (one warp per node, float4 lanes) ----------------
__global__ void head_kernel(const float* __restrict__ feat, const float* __restrict__ h,
                            const float* __restrict__ Wp, const float* __restrict__ bp,
                            const float* __restrict__ Wsv, const float* __restrict__ bsv,
                            float* __restrict__ praw, float* __restrict__ sisr, int N, int NN)
{
    int w = (blockIdx.x * blockDim.x + threadIdx.x) >> 5;
    int lane = threadIdx.x & 31;
    if (w >= N) return;
    int b = w / NN;
    const int c = lane * 4;
    float4 f  = *reinterpret_cast<const float4*>(feat + (size_t)w * 128 + c);
    float4 hh = *reinterpret_cast<const float4*>(h + b * 128 + c);
    float4 wp = *reinterpret_cast<const float4*>(Wp + c);
    float4 ws = *reinterpret_cast<const float4*>(Wsv + c);
    float4 xg;
    xg.x = f.x * hh.x; xg.y = f.y * hh.y; xg.z = f.z * hh.z; xg.w = f.w * hh.w;
    float p = xg.x * wp.x + xg.y * wp.y + xg.z * wp.z + xg.w * wp.w;
    float s = xg.x * ws.x + xg.y * ws.y + xg.z * ws.z + xg.w * ws.w;
    for (int off = 16; off; off >>= 1) {
        p += __shfl_xor_sync(0xffffffffu, p, off);
        s += __shfl_xor_sync(0xffffffffu, s, off);
    }
    if (lane == 0) {
        praw[w] = p + bp[0];
        sisr[w] = 1.f / (1.f + expf(-(s + bsv[0])));
    }
}

// ---------------- softmax over prob[:, 1:] per batch ----------------
__global__ void softmax_kernel(const float* __restrict__ praw, float* __restrict__ prob, int NN)
{
    __shared__ float red[512];
    int b = blockIdx.x, t = threadIdx.x;
    int n = t + 1;
    float v = (n < NN) ? praw[b * NN + n] : -1e30f;
    red[t] = v; __syncthreads();
    for (int off = 256; off; off >>= 1) {
        if (t < off) red[t] = fmaxf(red[t], red[t + off]);
        __syncthreads();
    }
    float m = red[0];
    __syncthreads();
    float e = (n < NN) ? expf(v - m) : 0.f;
    red[t] = e; __syncthreads();
    for (int off = 256; off; off >>= 1) {
        if (t < off) red[t] = red[t] + red[t + off];
        __syncthreads();
    }
    float sum = red[0];
    if (n < NN) prob[b * (NN - 1) + t] = e / sum;
}

// ---------------- launch ----------------
extern "C" void kernel_launch(void* const* d_in, const int* in_sizes, int n_in,
                              void* d_out, int out_size)
{
    const float* x      = (const float*)d_in[0];
    const int*   e0     = (const int*)  d_in[1];
    const int*   e1     = (const int*)  d_in[2];
    const float* state  = (const float*)d_in[3];
    const float* input_ = (const float*)d_in[4];
    const float* W_in   = (const float*)d_in[5];
    const float* W_z    = (const float*)d_in[6];
    const float* W_r    = (const float*)d_in[7];
    const float* W_h    = (const float*)d_in[8];
    const float* Wlin[2] = { (const float*)d_in[9],  (const float*)d_in[13] };
    const float* blin[2] = { (const float*)d_in[10], (const float*)d_in[14] };
    const float* Wat [2] = { (const float*)d_in[11], (const float*)d_in[15] };
    const float* bat [2] = { (const float*)d_in[12], (const float*)d_in[16] };
    const float* Wp     = (const float*)d_in[17];
    const float* bp     = (const float*)d_in[18];
    const float* Wsv    = (const float*)d_in[19];
    const float* bsv    = (const float*)d_in[20];

    const int N    = in_sizes[0] / 128;
    const int E    = in_sizes[1] / 2;
    const int B    = in_sizes[3] / 128;
    const int L    = in_sizes[4] / (B * 128);
    const int NN   = N / B;
    const int Etot = E + N;

    float *yp, *aip, *ajp, *featp, *hp, *prawp;
    int *cntp, *rowp, *curp, *srcp, *auxp;
    __nv_bfloat16 *wlinH, *wlinL, *watH, *watL;
    cudaGetSymbolAddress((void**)&yp,    g_y);
    cudaGetSymbolAddress((void**)&aip,   g_ai);
    cudaGetSymbolAddress((void**)&ajp,   g_aj);
    cudaGetSymbolAddress((void**)&featp, g_feat);
    cudaGetSymbolAddress((void**)&hp,    g_h);
    cudaGetSymbolAddress((void**)&prawp, g_praw);
    cudaGetSymbolAddress((void**)&cntp,  g_cnt);
    cudaGetSymbolAddress((void**)&rowp,  g_rowptr);
    cudaGetSymbolAddress((void**)&curp,  g_cursor);
    cudaGetSymbolAddress((void**)&srcp,  g_srcs);
    cudaGetSymbolAddress((void**)&auxp,  g_aux);
    cudaGetSymbolAddress((void**)&wlinH, g_wlinH);
    cudaGetSymbolAddress((void**)&wlinL, g_wlinL);
    cudaGetSymbolAddress((void**)&watH,  g_watH);
    cudaGetSymbolAddress((void**)&watL,  g_watL);

    float* out      = (float*)d_out;
    float* out_prob = out;
    float* out_sisr = out + (size_t)B * (NN - 1);
    float* out_h    = out + (size_t)B * (NN - 1) + (size_t)B * NN;

    // dynamic smem: A hi/lo (M_TILE*128*2*2B) + biasRep (16*N_OUT*4B)
    const int smN128 = 128 * 128 * 2 * 2 + 16 * 128 * 4;   // 65536 + 8192  = 73728
    const int smN256 = 64 * 128 * 2 * 2  + 16 * 256 * 4;   // 32768 + 16384 = 49152
    cudaFuncSetAttribute(gemm_wmma_kernel<128>, cudaFuncAttributeMaxDynamicSharedMemorySize, smN128);
    cudaFuncSetAttribute(gemm_wmma_kernel<256>, cudaFuncAttributeMaxDynamicSharedMemorySize, smN256);

    const int nbScan = (N + 255) / 256;
    const int gHist  = (Etot + 255) / 256;
    const int gWarp  = (N * 32 + 255) / 256;
    const int gTc128 = (N + 127) / 128;
    const int gTc256 = (N + 63) / 64;

    gru_kernel<<<B, 128>>>(state, input_, W_in, W_z, W_r, W_h, hp, out_h, L);           // 1

    for (int layer = 0; layer < 2; layer++) {
        const int* ei = layer ? e1 : e0;           // [2, E]: row 0 = src, row 1 = dst
        const float* Ain = layer ? featp : x;

        prep_w_kernel<<<192, 256>>>(Wlin[layer], Wat[layer], wlinH, wlinL, watH, watL); // 2
        zero_kernel  <<<nbScan, 256>>>(cntp, N);                                        // 3

        // y = A@Wlin^T + blin   (4th launch overall -> ncu capture slot)
        gemm_wmma_kernel<128><<<gTc128, 256, smN128>>>(Ain, wlinH, wlinL, blin[layer],
                                                       yp, yp, N);                      // 4

        hist_kernel   <<<gHist, 256>>>(ei + E, E, N, cntp);
        scan1_kernel  <<<nbScan, 256>>>(cntp, N, rowp, auxp);
        scan2_kernel  <<<1, 256>>>(auxp, nbScan, N, Etot, rowp);
        scan3_kernel  <<<nbScan, 256>>>(rowp, auxp, curp, N);
        scatter_kernel<<<gHist, 256>>>(ei, ei + E, E, N, curp, srcp);

        // fused attention: cols 0-127 -> ai (+b_attn), cols 128-255 -> aj
        gemm_wmma_kernel<256><<<gTc256, 256, smN256>>>(yp, watH, watL, bat[layer],
                                                       aip, ajp, N);

        edge_agg_kernel<<<gWarp, 256>>>(rowp, srcp, aip, ajp, yp, featp, N);
    }

    head_kernel   <<<gWarp, 256>>>(featp, hp, Wp, bp, Wsv, bsv, prawp, out_sisr, N, NN);
    softmax_kernel<<<B, 512>>>(prawp, out_prob, NN);
}

// round 14
// speedup vs baseline: 1.3796x; 1.0822x over previous
#include <cuda_runtime.h>
#include <cuda_bf16.h>
#include <mma.h>
#include <cstdint>
#include <cstdio>

using namespace nvcuda;

// ---------------- problem-fixed constants ----------------
#define DD 128
#define MAXN 32000
#define MAXE 290000

// ---------------- scratch (static device globals; no allocs allowed) ----------------
__device__ __align__(16) float g_y   [MAXN * DD];
__device__ __align__(16) float g_ai  [MAXN * DD];
__device__ __align__(16) float g_aj  [MAXN * DD];
__device__ __align__(16) float g_feat[MAXN * DD];
__device__ __align__(16) float g_h   [64 * DD];
__device__ __align__(16) float g_praw[MAXN];
__device__ int g_cnt   [MAXN];
__device__ int g_rowptr[MAXN + 1];
__device__ int g_cursor[MAXN];
__device__ int g_srcs  [MAXE];
__device__ int g_aux   [256];
// bf16 hi/lo weight images, row-major [n][k] (k contiguous)
__device__ __align__(16) __nv_bfloat16 g_wlinH[128 * 128];
__device__ __align__(16) __nv_bfloat16 g_wlinL[128 * 128];
__device__ __align__(16) __nv_bfloat16 g_watH [256 * 128];
__device__ __align__(16) __nv_bfloat16 g_watL [256 * 128];

// ---------------- weight prep: fp32 -> bf16 hi/lo (row-major) ----------------
__global__ void prep_w_kernel(const float* __restrict__ Wlin, const float* __restrict__ Wat,
                              __nv_bfloat16* __restrict__ linH, __nv_bfloat16* __restrict__ linL,
                              __nv_bfloat16* __restrict__ atH,  __nv_bfloat16* __restrict__ atL)
{
    int i = blockIdx.x * blockDim.x + threadIdx.x;
    if (i >= 16384 + 32768) return;
    float v;
    __nv_bfloat16 *dh, *dl;
    int o;
    if (i < 16384) {
        int n = i >> 7, k = i & 127;
        v = Wlin[n * 128 + k];
        dh = linH; dl = linL; o = i;
    } else {
        int j = i - 16384;
        int n = j >> 7, k = j & 127;
        v = (n < 128) ? Wat[n * 256 + k] : Wat[(n - 128) * 256 + 128 + k];
        dh = atH; dl = atL; o = j;
    }
    __nv_bfloat16 h = __float2bfloat16(v);
    __nv_bfloat16 l = __float2bfloat16(v - __bfloat162float(h));
    dh[o] = h;
    dl[o] = l;
}

// ---------------- wmma GEMM v4 ----------------
// C[M x N_OUT] = A[M x 128] @ W[N_OUT x 128]^T, bf16 hi/lo 3-product split, fp32 acc.
// Warp tile 64m x 32n (acc 4x2): per k-step only 4 GLOBAL B-frag loads feed 24 MMAs
// (A frags come from 29-cyc smem). __launch_bounds__(256,2) caps regs at 128 so
// 2 blocks/SM co-reside (16 warps) to hide the remaining global latency.
// N_OUT=128: M_TILE=128 (2 m-pos x 4 n-pos), bias0 on all cols -> C0.
// N_OUT=256: M_TILE=64  (1 m-pos x 8 n-pos), cols<128 -> C0 (+bias0), cols>=128 -> C1.
template <int N_OUT>
__global__ __launch_bounds__(256, 2) void gemm_wmma_kernel(
    const float* __restrict__ A,
    const __nv_bfloat16* __restrict__ WH, const __nv_bfloat16* __restrict__ WL,
    const float* __restrict__ bias0,
    float* __restrict__ C0, float* __restrict__ C1, int M)
{
    constexpr int MPOS   = (N_OUT == 128) ? 2 : 1;
    constexpr int M_TILE = MPOS * 64;
    extern __shared__ char smc[];
    __nv_bfloat16* Ahi = reinterpret_cast<__nv_bfloat16*>(smc);
    __nv_bfloat16* Alo = Ahi + M_TILE * 128;
    float* biasRep     = reinterpret_cast<float*>(Alo + M_TILE * 128);   // [16][N_OUT]

    const int tid = threadIdx.x;
    const int wid = tid >> 5;
    const int m0 = blockIdx.x * M_TILE;

    // stage A: fp32 -> bf16 hi/lo (coalesced: warp spans one row's k)
    for (int idx = tid; idx < M_TILE * 32; idx += 256) {
        int row = idx >> 5, k = (idx & 31) << 2;
        int m = m0 + row;
        float4 v = make_float4(0.f, 0.f, 0.f, 0.f);
        if (m < M) v = *reinterpret_cast<const float4*>(A + (size_t)m * 128 + k);
        __nv_bfloat16 h0 = __float2bfloat16(v.x), h1 = __float2bfloat16(v.y);
        __nv_bfloat16 h2 = __float2bfloat16(v.z), h3 = __float2bfloat16(v.w);
        __nv_bfloat16 l0 = __float2bfloat16(v.x - __bfloat162float(h0));
        __nv_bfloat16 l1 = __float2bfloat16(v.y - __bfloat162float(h1));
        __nv_bfloat16 l2 = __float2bfloat16(v.z - __bfloat162float(h2));
        __nv_bfloat16 l3 = __float2bfloat16(v.w - __bfloat162float(h3));
        uint32_t hA = ((uint32_t)__bfloat16_as_ushort(h1) << 16) | __bfloat16_as_ushort(h0);
        uint32_t hB = ((uint32_t)__bfloat16_as_ushort(h3) << 16) | __bfloat16_as_ushort(h2);
        uint32_t lA = ((uint32_t)__bfloat16_as_ushort(l1) << 16) | __bfloat16_as_ushort(l0);
        uint32_t lB = ((uint32_t)__bfloat16_as_ushort(l3) << 16) | __bfloat16_as_ushort(l2);
        *reinterpret_cast<uint2*>(Ahi + row * 128 + k) = make_uint2(hA, hB);
        *reinterpret_cast<uint2*>(Alo + row * 128 + k) = make_uint2(lA, lB);
    }
    // stage bias-replicated tile [16][N_OUT] (cols >= 128 get 0)
    for (int idx = tid; idx < 16 * N_OUT; idx += 256) {
        int c = idx % N_OUT;
        biasRep[idx] = (c < 128) ? bias0[c] : 0.f;
    }
    __syncthreads();

    const int m_sub  = (wid % MPOS) * 64;     // warp's 64 m-rows within tile
    const int n_base = (wid / MPOS) * 32;     // warp's 32 n-cols

    wmma::fragment<wmma::accumulator, 16, 16, 16, float> acc[4][2];
#pragma unroll
    for (int i = 0; i < 4; i++)
#pragma unroll
        for (int t = 0; t < 2; t++)
            wmma::load_matrix_sync(acc[i][t], biasRep + n_base + t * 16, N_OUT, wmma::mem_row_major);

#pragma unroll
    for (int s = 0; s < 8; s++) {
        const int k0 = s * 16;
        // 4 global B-frag loads per k-step (reused by 4 m-subtiles / 24 MMAs)
        wmma::fragment<wmma::matrix_b, 16, 16, 16, __nv_bfloat16, wmma::col_major> bH[2], bL[2];
#pragma unroll
        for (int t = 0; t < 2; t++) {
            const int n0 = n_base + t * 16;
            wmma::load_matrix_sync(bH[t], WH + (size_t)n0 * 128 + k0, 128);
            wmma::load_matrix_sync(bL[t], WL + (size_t)n0 * 128 + k0, 128);
        }
#pragma unroll
        for (int i = 0; i < 4; i++) {
            wmma::fragment<wmma::matrix_a, 16, 16, 16, __nv_bfloat16, wmma::row_major> aH, aL;
            wmma::load_matrix_sync(aH, Ahi + (m_sub + i * 16) * 128 + k0, 128);
            wmma::load_matrix_sync(aL, Alo + (m_sub + i * 16) * 128 + k0, 128);
#pragma unroll
            for (int t = 0; t < 2; t++) {
                wmma::mma_sync(acc[i][t], aH, bH[t], acc[i][t]);
                wmma::mma_sync(acc[i][t], aH, bL[t], acc[i][t]);
                wmma::mma_sync(acc[i][t], aL, bH[t], acc[i][t]);
            }
        }
    }

    if (m0 + M_TILE <= M) {
        // full tile: direct stores
#pragma unroll
        for (int i = 0; i < 4; i++) {
            const int m = m0 + m_sub + i * 16;
#pragma unroll
            for (int t = 0; t < 2; t++) {
                const int n0 = n_base + t * 16;
                float* dst = (n0 < 128) ? (C0 + (size_t)m * 128 + n0)
                                        : (C1 + (size_t)m * 128 + (n0 - 128));
                wmma::store_matrix_sync(dst, acc[i][t], 128, wmma::mem_row_major);
            }
        }
    } else {
        // tail: stage through per-warp scratch in the (now dead) A region
        __syncthreads();
        float* scr = reinterpret_cast<float*>(smc) + wid * 256;
        const int lane = tid & 31;
#pragma unroll
        for (int i = 0; i < 4; i++) {
            const int m = m0 + m_sub + i * 16;
#pragma unroll
            for (int t = 0; t < 2; t++) {
                const int n0 = n_base + t * 16;
                wmma::store_matrix_sync(scr, acc[i][t], 16, wmma::mem_row_major);
                __syncwarp();
                for (int e = lane; e < 256; e += 32) {
                    int r = e >> 4, c = e & 15;
                    int mm = m + r;
                    if (mm < M) {
                        float* dst = (n0 < 128) ? (C0 + (size_t)mm * 128 + n0 + c)
                                                : (C1 + (size_t)mm * 128 + (n0 - 128) + c);
                        *dst = scr[r * 16 + c];
                    }
                }
                __syncwarp();
            }
        }
    }
}

// ---------------- CSR build ----------------
__global__ void zero_kernel(int* __restrict__ p, int N) {
    int i = blockIdx.x * blockDim.x + threadIdx.x;
    if (i < N) p[i] = 0;
}

__global__ void hist_kernel(const int* __restrict__ dst, int E, int N, int* __restrict__ cnt) {
    int i = blockIdx.x * blockDim.x + threadIdx.x;
    if (i < E + N) {
        int d = (i < E) ? dst[i] : (i - E);
        atomicAdd(cnt + d, 1);
    }
}

__device__ __forceinline__ int block_incl_scan256(int v, int tid) {
    __shared__ int ws[8];
    int lane = tid & 31, wid = tid >> 5;
#pragma unroll
    for (int off = 1; off < 32; off <<= 1) {
        int t = __shfl_up_sync(0xffffffffu, v, off);
        if (lane >= off) v += t;
    }
    if (lane == 31) ws[wid] = v;
    __syncthreads();
    if (wid == 0) {
        int s = (lane < 8) ? ws[lane] : 0;
#pragma unroll
        for (int off = 1; off < 8; off <<= 1) {
            int t = __shfl_up_sync(0xffffffffu, s, off);
            if (lane >= off) s += t;
        }
        if (lane < 8) ws[lane] = s;
    }
    __syncthreads();
    if (wid > 0) v += ws[wid - 1];
    return v;
}

__global__ void scan1_kernel(const int* __restrict__ cnt, int N, int* __restrict__ rowptr, int* __restrict__ aux) {
    int t = threadIdx.x;
    int gid = blockIdx.x * 256 + t;
    int c = (gid < N) ? cnt[gid] : 0;
    int incl = block_incl_scan256(c, t);
    if (gid < N) rowptr[gid] = incl - c;
    if (t == 255) aux[blockIdx.x] = incl;
}

__global__ void scan2_kernel(int* __restrict__ aux, int nb, int N, int Etot, int* __restrict__ rowptr) {
    int t = threadIdx.x;
    int v0 = (t < nb) ? aux[t] : 0;
    int incl = block_incl_scan256(v0, t);
    if (t < nb) aux[t] = incl - v0;
    if (t == 0) rowptr[N] = Etot;
}

__global__ void scan3_kernel(int* __restrict__ rowptr, const int* __restrict__ aux,
                             int* __restrict__ cursor, int N) {
    int gid = blockIdx.x * blockDim.x + threadIdx.x;
    if (gid < N) {
        int v = rowptr[gid] + aux[blockIdx.x];
        rowptr[gid] = v;
        cursor[gid] = v;
    }
}

__global__ void scatter_kernel(const int* __restrict__ src, const int* __restrict__ dst,
                               int E, int N, int* __restrict__ cursor, int* __restrict__ out) {
    int i = blockIdx.x * blockDim.x + threadIdx.x;
    if (i < E + N) {
        int s, d;
        if (i < E) { s = src[i]; d = dst[i]; }
        else       { s = i - E; d = i - E; }
        int pos = atomicAdd(cursor + d, 1);
        out[pos] = s;
    }
}

// ---------------- GAT edge softmax + aggregate (one warp per dst node, float4 lanes) ----------------
__global__ void edge_agg_kernel(const int* __restrict__ rowptr, const int* __restrict__ srcs,
                                const float* __restrict__ ai, const float* __restrict__ aj,
                                const float* __restrict__ y, float* __restrict__ out, int N)
{
    int w = (blockIdx.x * blockDim.x + threadIdx.x) >> 5;
    int lane = threadIdx.x & 31;
    if (w >= N) return;
    const int c = lane * 4;
    float4 ai4 = *reinterpret_cast<const float4*>(ai + (size_t)w * 128 + c);
    float4 den = make_float4(0.f, 0.f, 0.f, 0.f);
    float4 num = make_float4(0.f, 0.f, 0.f, 0.f);
    int e0 = rowptr[w], e1 = rowptr[w + 1];
    int s_next = (e0 < e1) ? srcs[e0] : 0;
    for (int j = e0; j < e1; j++) {
        int s = s_next;
        if (j + 1 < e1) s_next = srcs[j + 1];
        float4 aj4 = *reinterpret_cast<const float4*>(aj + (size_t)s * 128 + c);
        float4 y4  = *reinterpret_cast<const float4*>(y  + (size_t)s * 128 + c);
        float a, e;
        a = ai4.x + aj4.x; a = fmaxf(a, 0.2f * a); e = __expf(a); den.x += e; num.x += e * y4.x;
        a = ai4.y + aj4.y; a = fmaxf(a, 0.2f * a); e = __expf(a); den.y += e; num.y += e * y4.y;
        a = ai4.z + aj4.z; a = fmaxf(a, 0.2f * a); e = __expf(a); den.z += e; num.z += e * y4.z;
        a = ai4.w + aj4.w; a = fmaxf(a, 0.2f * a); e = __expf(a); den.w += e; num.w += e * y4.w;
    }
    float4 o;
    o.x = num.x / (den.x + 1e-16f);
    o.y = num.y / (den.y + 1e-16f);
    o.z = num.z / (den.z + 1e-16f);
    o.w = num.w / (den.w + 1e-16f);
    *reinterpret_cast<float4*>(out + (size_t)w * 128 + c) = o;
}

// ---------------- GRU ----------------
__global__ void gru_kernel(const float* __restrict__ state, const float* __restrict__ input_,
                           const float* __restrict__ W_in, const float* __restrict__ W_z,
                           const float* __restrict__ W_r, const float* __restrict__ W_h,
                           float* __restrict__ h_out, float* __restrict__ h_out2, int L)
{
    __shared__ float mi[128], inp[128], st[128], rs[128], zz[128];
    int b = blockIdx.x, t = threadIdx.x;
    const float* ib = input_ + (size_t)b * L * 128;
    float s = 0.f;
    for (int l = 0; l < L; l++) s += ib[l * 128 + t];
    mi[t] = s / (float)L;
    st[t] = state[b * 128 + t];
    __syncthreads();
    {
        float acc = 0.f;
        const float* wr = W_in + t * 128;
        for (int d = 0; d < 128; d++) acc += mi[d] * wr[d];
        inp[t] = acc;
    }
    __syncthreads();
    float az = 0.f, ar = 0.f;
    {
        const float* wz = W_z + t * 256;
        const float* wr = W_r + t * 256;
        for (int d = 0; d < 128; d++) { az += st[d] * wz[d];        ar += st[d] * wr[d]; }
        for (int d = 0; d < 128; d++) { az += inp[d] * wz[128 + d]; ar += inp[d] * wr[128 + d]; }
    }
    float z = 1.f / (1.f + expf(-az));
    float r = 1.f / (1.f + expf(-ar));
    zz[t] = z;
    rs[t] = r * st[t];
    __syncthreads();
    float ah = 0.f;
    {
        const float* wh = W_h + t * 256;
        for (int d = 0; d < 128; d++) ah += rs[d] * wh[d];
        for (int d = 0; d < 128; d++) ah += inp[d] * wh[128 + d];
    }
    float ht = tanhf(ah);
    float h = (1.f - zz[t]) * st[t] + zz[t] * ht;
    h_out[b * 128 + t] = h;
    h_out2[b * 128 + t] = h;
}

// ---------------- head: prob logits + sisr (one warp per node, float4 lanes) ----------------
__global__ void head_kernel(const float* __restrict__ feat, const float* __restrict__ h,
                            const float* __restrict__ Wp, const float* __restrict__ bp,
                            const float* __restrict__ Wsv, const float* __restrict__ bsv,
                            float* __restrict__ praw, float* __restrict__ sisr, int N, int NN)
{
    int w = (blockIdx.x * blockDim.x + threadIdx.x) >> 5;
    int lane = threadIdx.x & 31;
    if (w >= N) return;
    int b = w / NN;
    const int c = lane * 4;
    float4 f  = *reinterpret_cast<const float4*>(feat + (size_t)w * 128 + c);
    float4 hh = *reinterpret_cast<const float4*>(h + b * 128 + c);
    float4 wp = *reinterpret_cast<const float4*>(Wp + c);
    float4 ws = *reinterpret_cast<const float4*>(Wsv + c);
    float4 xg;
    xg.x = f.x * hh.x; xg.y = f.y * hh.y; xg.z = f.z * hh.z; xg.w = f.w * hh.w;
    float p = xg.x * wp.x + xg.y * wp.y + xg.z * wp.z + xg.w * wp.w;
    float s = xg.x * ws.x + xg.y * ws.y + xg.z * ws.z + xg.w * ws.w;
    for (int off = 16; off; off >>= 1) {
        p += __shfl_xor_sync(0xffffffffu, p, off);
        s += __shfl_xor_sync(0xffffffffu, s, off);
    }
    if (lane == 0) {
        praw[w] = p + bp[0];
        sisr[w] = 1.f / (1.f + expf(-(s + bsv[0])));
    }
}

// ---------------- softmax over prob[:, 1:] per batch ----------------
__global__ void softmax_kernel(const float* __restrict__ praw, float* __restrict__ prob, int NN)
{
    __shared__ float red[512];
    int b = blockIdx.x, t = threadIdx.x;
    int n = t + 1;
    float v = (n < NN) ? praw[b * NN + n] : -1e30f;
    red[t] = v; __syncthreads();
    for (int off = 256; off; off >>= 1) {
        if (t < off) red[t] = fmaxf(red[t], red[t + off]);
        __syncthreads();
    }
    float m = red[0];
    __syncthreads();
    float e = (n < NN) ? expf(v - m) : 0.f;
    red[t] = e; __syncthreads();
    for (int off = 256; off; off >>= 1) {
        if (t < off) red[t] = red[t] + red[t + off];
        __syncthreads();
    }
    float sum = red[0];
    if (n < NN) prob[b * (NN - 1) + t] = e / sum;
}

// ---------------- launch ----------------
extern "C" void kernel_launch(void* const* d_in, const int* in_sizes, int n_in,
                              void* d_out, int out_size)
{
    const float* x      = (const float*)d_in[0];
    const int*   e0     = (const int*)  d_in[1];
    const int*   e1     = (const int*)  d_in[2];
    const float* state  = (const float*)d_in[3];
    const float* input_ = (const float*)d_in[4];
    const float* W_in   = (const float*)d_in[5];
    const float* W_z    = (const float*)d_in[6];
    const float* W_r    = (const float*)d_in[7];
    const float* W_h    = (const float*)d_in[8];
    const float* Wlin[2] = { (const float*)d_in[9],  (const float*)d_in[13] };
    const float* blin[2] = { (const float*)d_in[10], (const float*)d_in[14] };
    const float* Wat [2] = { (const float*)d_in[11], (const float*)d_in[15] };
    const float* bat [2] = { (const float*)d_in[12], (const float*)d_in[16] };
    const float* Wp     = (const float*)d_in[17];
    const float* bp     = (const float*)d_in[18];
    const float* Wsv    = (const float*)d_in[19];
    const float* bsv    = (const float*)d_in[20];

    const int N    = in_sizes[0] / 128;
    const int E    = in_sizes[1] / 2;
    const int B    = in_sizes[3] / 128;
    const int L    = in_sizes[4] / (B * 128);
    const int NN   = N / B;
    const int Etot = E + N;

    float *yp, *aip, *ajp, *featp, *hp, *prawp;
    int *cntp, *rowp, *curp, *srcp, *auxp;
    __nv_bfloat16 *wlinH, *wlinL, *watH, *watL;
    cudaGetSymbolAddress((void**)&yp,    g_y);
    cudaGetSymbolAddress((void**)&aip,   g_ai);
    cudaGetSymbolAddress((void**)&ajp,   g_aj);
    cudaGetSymbolAddress((void**)&featp, g_feat);
    cudaGetSymbolAddress((void**)&hp,    g_h);
    cudaGetSymbolAddress((void**)&prawp, g_praw);
    cudaGetSymbolAddress((void**)&cntp,  g_cnt);
    cudaGetSymbolAddress((void**)&rowp,  g_rowptr);
    cudaGetSymbolAddress((void**)&curp,  g_cursor);
    cudaGetSymbolAddress((void**)&srcp,  g_srcs);
    cudaGetSymbolAddress((void**)&auxp,  g_aux);
    cudaGetSymbolAddress((void**)&wlinH, g_wlinH);
    cudaGetSymbolAddress((void**)&wlinL, g_wlinL);
    cudaGetSymbolAddress((void**)&watH,  g_watH);
    cudaGetSymbolAddress((void**)&watL,  g_watL);

    float* out      = (float*)d_out;
    float* out_prob = out;
    float* out_sisr = out + (size_t)B * (NN - 1);
    float* out_h    = out + (size_t)B * (NN - 1) + (size_t)B * NN;

    // dynamic smem: A hi/lo (M_TILE*128*2*2B) + biasRep (16*N_OUT*4B)
    const int smN128 = 128 * 128 * 2 * 2 + 16 * 128 * 4;   // 65536 + 8192  = 73728
    const int smN256 = 64 * 128 * 2 * 2  + 16 * 256 * 4;   // 32768 + 16384 = 49152
    cudaFuncSetAttribute(gemm_wmma_kernel<128>, cudaFuncAttributeMaxDynamicSharedMemorySize, smN128);
    cudaFuncSetAttribute(gemm_wmma_kernel<256>, cudaFuncAttributeMaxDynamicSharedMemorySize, smN256);

    const int nbScan = (N + 255) / 256;
    const int gHist  = (Etot + 255) / 256;
    const int gWarp  = (N * 32 + 255) / 256;
    const int gTc128 = (N + 127) / 128;
    const int gTc256 = (N + 63) / 64;

    gru_kernel<<<B, 128>>>(state, input_, W_in, W_z, W_r, W_h, hp, out_h, L);           // 1

    for (int layer = 0; layer < 2; layer++) {
        const int* ei = layer ? e1 : e0;           // [2, E]: row 0 = src, row 1 = dst
        const float* Ain = layer ? featp : x;

        prep_w_kernel<<<192, 256>>>(Wlin[layer], Wat[layer], wlinH, wlinL, watH, watL); // 2
        zero_kernel  <<<nbScan, 256>>>(cntp, N);                                        // 3

        // y = A@Wlin^T + blin   (4th launch overall -> ncu capture slot)
        gemm_wmma_kernel<128><<<gTc128, 256, smN128>>>(Ain, wlinH, wlinL, blin[layer],
                                                       yp, yp, N);                      // 4

        hist_kernel   <<<gHist, 256>>>(ei + E, E, N, cntp);
        scan1_kernel  <<<nbScan, 256>>>(cntp, N, rowp, auxp);
        scan2_kernel  <<<1, 256>>>(auxp, nbScan, N, Etot, rowp);
        scan3_kernel  <<<nbScan, 256>>>(rowp, auxp, curp, N);
        scatter_kernel<<<gHist, 256>>>(ei, ei + E, E, N, curp, srcp);

        // fused attention: cols 0-127 -> ai (+b_attn), cols 128-255 -> aj
        gemm_wmma_kernel<256><<<gTc256, 256, smN256>>>(yp, watH, watL, bat[layer],
                                                       aip, ajp, N);

        edge_agg_kernel<<<gWarp, 256>>>(rowp, srcp, aip, ajp, yp, featp, N);
    }

    head_kernel   <<<gWarp, 256>>>(featp, hp, Wp, bp, Wsv, bsv, prawp, out_sisr, N, NN);
    softmax_kernel<<<B, 512>>>(prawp, out_prob, NN);
}

// round 17
// speedup vs baseline: 1.7265x; 1.2514x over previous
#include <cuda_runtime.h>
#include <cuda_bf16.h>
#include <mma.h>
#include <cstdint>
#include <cstdio>

using namespace nvcuda;

// ---------------- problem-fixed constants ----------------
#define DD 128
#define MAXN 32000
#define MAXE 290000

#define LDA 136      // padded bf16 row stride for A/W smem tiles (LDSM conflict-free)
#define LDBIAS 132   // padded f32 row stride for bias tile

// ---------------- scratch (static device globals; no allocs allowed) ----------------
__device__ __align__(16) float g_y   [MAXN * DD];
__device__ __align__(16) float g_ai  [MAXN * DD];
__device__ __align__(16) float g_aj  [MAXN * DD];
__device__ __align__(16) float g_feat[MAXN * DD];
__device__ __align__(16) float g_h   [64 * DD];
__device__ __align__(16) float g_praw[MAXN];
__device__ int g_cnt   [MAXN];
__device__ int g_rowptr[MAXN + 1];
__device__ int g_cursor[MAXN];
__device__ int g_srcs  [MAXE];
__device__ int g_aux   [256];
// bf16 hi/lo weight images, row-major [n][k] (k contiguous)
__device__ __align__(16) __nv_bfloat16 g_wlinH[128 * 128];
__device__ __align__(16) __nv_bfloat16 g_wlinL[128 * 128];
__device__ __align__(16) __nv_bfloat16 g_watH [256 * 128];
__device__ __align__(16) __nv_bfloat16 g_watL [256 * 128];

// ---------------- weight prep: fp32 -> bf16 hi/lo (row-major) ----------------
__global__ void prep_w_kernel(const float* __restrict__ Wlin, const float* __restrict__ Wat,
                              __nv_bfloat16* __restrict__ linH, __nv_bfloat16* __restrict__ linL,
                              __nv_bfloat16* __restrict__ atH,  __nv_bfloat16* __restrict__ atL)
{
    int i = blockIdx.x * blockDim.x + threadIdx.x;
    if (i >= 16384 + 32768) return;
    float v;
    __nv_bfloat16 *dh, *dl;
    int o;
    if (i < 16384) {
        int n = i >> 7, k = i & 127;
        v = Wlin[n * 128 + k];
        dh = linH; dl = linL; o = i;
    } else {
        int j = i - 16384;
        int n = j >> 7, k = j & 127;
        v = (n < 128) ? Wat[n * 256 + k] : Wat[(n - 128) * 256 + 128 + k];
        dh = atH; dl = atL; o = j;
    }
    __nv_bfloat16 h = __float2bfloat16(v);
    __nv_bfloat16 l = __float2bfloat16(v - __bfloat162float(h));
    dh[o] = h;
    dl[o] = l;
}

// ---------------- wmma GEMM v5 ----------------
// C[M x 128] = A[M x 128] @ W[128 x 128]^T (+bias), bf16 hi/lo 3-product split, fp32 acc.
// ALL fragment loads from smem with padded ldm=136 (272B row stride -> LDSM phases
// cover all 32 banks, conflict-free). M_TILE=64, 8 warps at 32m x 32n (acc 2x2).
// smem 110.25KB -> 2 blocks/SM (16 warps) for latency hiding.
__global__ __launch_bounds__(256, 2) void gemm_wmma_kernel(
    const float* __restrict__ A,
    const __nv_bfloat16* __restrict__ WH, const __nv_bfloat16* __restrict__ WL,
    const float* __restrict__ bias,
    float* __restrict__ C, int M)
{
    extern __shared__ char smc[];
    __nv_bfloat16* Wh  = reinterpret_cast<__nv_bfloat16*>(smc);   // [128][LDA]
    __nv_bfloat16* Wl  = Wh + 128 * LDA;
    __nv_bfloat16* Ahi = Wl + 128 * LDA;                          // [64][LDA]
    __nv_bfloat16* Alo = Ahi + 64 * LDA;
    float* biasRep     = reinterpret_cast<float*>(Alo + 64 * LDA);// [16][LDBIAS]

    const int tid = threadIdx.x;
    const int wid = tid >> 5;
    const int m0 = blockIdx.x * 64;

    // stage W: global row-major [128][128] -> smem [128][LDA]  (uint4 copy, coalesced)
    // row byte stride in smem = LDA*2 = 272 = 17 uint4
    for (int idx = tid; idx < 128 * 16; idx += 256) {
        int row = idx >> 4, c = idx & 15;
        reinterpret_cast<uint4*>(Wh)[row * 17 + c] = reinterpret_cast<const uint4*>(WH)[idx];
        reinterpret_cast<uint4*>(Wl)[row * 17 + c] = reinterpret_cast<const uint4*>(WL)[idx];
    }
    // stage A: fp32 -> bf16 hi/lo into [64][LDA] (warp spans one row's k, coalesced)
    for (int idx = tid; idx < 64 * 32; idx += 256) {
        int row = idx >> 5, k = (idx & 31) << 2;
        int m = m0 + row;
        float4 v = make_float4(0.f, 0.f, 0.f, 0.f);
        if (m < M) v = *reinterpret_cast<const float4*>(A + (size_t)m * 128 + k);
        __nv_bfloat16 h0 = __float2bfloat16(v.x), h1 = __float2bfloat16(v.y);
        __nv_bfloat16 h2 = __float2bfloat16(v.z), h3 = __float2bfloat16(v.w);
        __nv_bfloat16 l0 = __float2bfloat16(v.x - __bfloat162float(h0));
        __nv_bfloat16 l1 = __float2bfloat16(v.y - __bfloat162float(h1));
        __nv_bfloat16 l2 = __float2bfloat16(v.z - __bfloat162float(h2));
        __nv_bfloat16 l3 = __float2bfloat16(v.w - __bfloat162float(h3));
        uint32_t hA = ((uint32_t)__bfloat16_as_ushort(h1) << 16) | __bfloat16_as_ushort(h0);
        uint32_t hB = ((uint32_t)__bfloat16_as_ushort(h3) << 16) | __bfloat16_as_ushort(h2);
        uint32_t lA = ((uint32_t)__bfloat16_as_ushort(l1) << 16) | __bfloat16_as_ushort(l0);
        uint32_t lB = ((uint32_t)__bfloat16_as_ushort(l3) << 16) | __bfloat16_as_ushort(l2);
        *reinterpret_cast<uint2*>(Ahi + row * LDA + k) = make_uint2(hA, hB);
        *reinterpret_cast<uint2*>(Alo + row * LDA + k) = make_uint2(lA, lB);
    }
    // stage bias-replicated tile [16][LDBIAS]
    for (int idx = tid; idx < 16 * 128; idx += 256) {
        int r = idx >> 7, c = idx & 127;
        biasRep[r * LDBIAS + c] = bias ? bias[c] : 0.f;
    }
    __syncthreads();

    const int m_sub  = (wid & 1) * 32;       // warp's 32 m-rows within tile
    const int n_base = (wid >> 1) * 32;      // warp's 32 n-cols

    wmma::fragment<wmma::accumulator, 16, 16, 16, float> acc[2][2];
#pragma unroll
    for (int i = 0; i < 2; i++)
#pragma unroll
        for (int t = 0; t < 2; t++)
            wmma::load_matrix_sync(acc[i][t], biasRep + n_base + t * 16, LDBIAS, wmma::mem_row_major);

#pragma unroll
    for (int s = 0; s < 8; s++) {
        const int k0 = s * 16;
        wmma::fragment<wmma::matrix_b, 16, 16, 16, __nv_bfloat16, wmma::col_major> bH[2], bL[2];
#pragma unroll
        for (int t = 0; t < 2; t++) {
            const int n0 = n_base + t * 16;
            wmma::load_matrix_sync(bH[t], Wh + n0 * LDA + k0, LDA);
            wmma::load_matrix_sync(bL[t], Wl + n0 * LDA + k0, LDA);
        }
        wmma::fragment<wmma::matrix_a, 16, 16, 16, __nv_bfloat16, wmma::row_major> aH[2], aL[2];
#pragma unroll
        for (int i = 0; i < 2; i++) {
            wmma::load_matrix_sync(aH[i], Ahi + (m_sub + i * 16) * LDA + k0, LDA);
            wmma::load_matrix_sync(aL[i], Alo + (m_sub + i * 16) * LDA + k0, LDA);
        }
#pragma unroll
        for (int i = 0; i < 2; i++)
#pragma unroll
            for (int t = 0; t < 2; t++) {
                wmma::mma_sync(acc[i][t], aH[i], bH[t], acc[i][t]);
                wmma::mma_sync(acc[i][t], aH[i], bL[t], acc[i][t]);
                wmma::mma_sync(acc[i][t], aL[i], bH[t], acc[i][t]);
            }
    }

    if (m0 + 64 <= M) {
#pragma unroll
        for (int i = 0; i < 2; i++) {
            const int m = m0 + m_sub + i * 16;
#pragma unroll
            for (int t = 0; t < 2; t++)
                wmma::store_matrix_sync(C + (size_t)m * 128 + n_base + t * 16,
                                        acc[i][t], 128, wmma::mem_row_major);
        }
    } else {
        // tail: stage through per-warp scratch in the (now dead) A region
        __syncthreads();
        float* scr = reinterpret_cast<float*>(smc) + wid * 256;
        const int lane = tid & 31;
#pragma unroll
        for (int i = 0; i < 2; i++) {
            const int m = m0 + m_sub + i * 16;
#pragma unroll
            for (int t = 0; t < 2; t++) {
                const int n0 = n_base + t * 16;
                wmma::store_matrix_sync(scr, acc[i][t], 16, wmma::mem_row_major);
                __syncwarp();
                for (int e = lane; e < 256; e += 32) {
                    int r = e >> 4, c = e & 15;
                    int mm = m + r;
                    if (mm < M) C[(size_t)mm * 128 + n0 + c] = scr[r * 16 + c];
                }
                __syncwarp();
            }
        }
    }
}

#define GEMM_SMEM (128 * LDA * 2 * 2 + 64 * LDA * 2 * 2 + 16 * LDBIAS * 4)  // 112896

// ---------------- CSR build ----------------
__global__ void zero_kernel(int* __restrict__ p, int N) {
    int i = blockIdx.x * blockDim.x + threadIdx.x;
    if (i < N) p[i] = 0;
}

__global__ void hist_kernel(const int* __restrict__ dst, int E, int N, int* __restrict__ cnt) {
    int i = blockIdx.x * blockDim.x + threadIdx.x;
    if (i < E + N) {
        int d = (i < E) ? dst[i] : (i - E);
        atomicAdd(cnt + d, 1);
    }
}

__device__ __forceinline__ int block_incl_scan256(int v, int tid) {
    __shared__ int ws[8];
    int lane = tid & 31, wid = tid >> 5;
#pragma unroll
    for (int off = 1; off < 32; off <<= 1) {
        int t = __shfl_up_sync(0xffffffffu, v, off);
        if (lane >= off) v += t;
    }
    if (lane == 31) ws[wid] = v;
    __syncthreads();
    if (wid == 0) {
        int s = (lane < 8) ? ws[lane] : 0;
#pragma unroll
        for (int off = 1; off < 8; off <<= 1) {
            int t = __shfl_up_sync(0xffffffffu, s, off);
            if (lane >= off) s += t;
        }
        if (lane < 8) ws[lane] = s;
    }
    __syncthreads();
    if (wid > 0) v += ws[wid - 1];
    return v;
}

__global__ void scan1_kernel(const int* __restrict__ cnt, int N, int* __restrict__ rowptr, int* __restrict__ aux) {
    int t = threadIdx.x;
    int gid = blockIdx.x * 256 + t;
    int c = (gid < N) ? cnt[gid] : 0;
    int incl = block_incl_scan256(c, t);
    if (gid < N) rowptr[gid] = incl - c;
    if (t == 255) aux[blockIdx.x] = incl;
}

__global__ void scan2_kernel(int* __restrict__ aux, int nb, int N, int Etot, int* __restrict__ rowptr) {
    int t = threadIdx.x;
    int v0 = (t < nb) ? aux[t] : 0;
    int incl = block_incl_scan256(v0, t);
    if (t < nb) aux[t] = incl - v0;
    if (t == 0) rowptr[N] = Etot;
}

__global__ void scan3_kernel(int* __restrict__ rowptr, const int* __restrict__ aux,
                             int* __restrict__ cursor, int N) {
    int gid = blockIdx.x * blockDim.x + threadIdx.x;
    if (gid < N) {
        int v = rowptr[gid] + aux[blockIdx.x];
        rowptr[gid] = v;
        cursor[gid] = v;
    }
}

__global__ void scatter_kernel(const int* __restrict__ src, const int* __restrict__ dst,
                               int E, int N, int* __restrict__ cursor, int* __restrict__ out) {
    int i = blockIdx.x * blockDim.x + threadIdx.x;
    if (i < E + N) {
        int s, d;
        if (i < E) { s = src[i]; d = dst[i]; }
        else       { s = i - E; d = i - E; }
        int pos = atomicAdd(cursor + d, 1);
        out[pos] = s;
    }
}

// ---------------- GAT edge softmax + aggregate (one warp per dst node, float4 lanes) ----------------
__global__ void edge_agg_kernel(const int* __restrict__ rowptr, const int* __restrict__ srcs,
                                const float* __restrict__ ai, const float* __restrict__ aj,
                                const float* __restrict__ y, float* __restrict__ out, int N)
{
    int w = (blockIdx.x * blockDim.x + threadIdx.x) >> 5;
    int lane = threadIdx.x & 31;
    if (w >= N) return;
    const int c = lane * 4;
    float4 ai4 = *reinterpret_cast<const float4*>(ai + (size_t)w * 128 + c);
    float4 den = make_float4(0.f, 0.f, 0.f, 0.f);
    float4 num = make_float4(0.f, 0.f, 0.f, 0.f);
    int e0 = rowptr[w], e1 = rowptr[w + 1];
    int s_next = (e0 < e1) ? srcs[e0] : 0;
    for (int j = e0; j < e1; j++) {
        int s = s_next;
        if (j + 1 < e1) s_next = srcs[j + 1];
        float4 aj4 = *reinterpret_cast<const float4*>(aj + (size_t)s * 128 + c);
        float4 y4  = *reinterpret_cast<const float4*>(y  + (size_t)s * 128 + c);
        float a, e;
        a = ai4.x + aj4.x; a = fmaxf(a, 0.2f * a); e = __expf(a); den.x += e; num.x += e * y4.x;
        a = ai4.y + aj4.y; a = fmaxf(a, 0.2f * a); e = __expf(a); den.y += e; num.y += e * y4.y;
        a = ai4.z + aj4.z; a = fmaxf(a, 0.2f * a); e = __expf(a); den.z += e; num.z += e * y4.z;
        a = ai4.w + aj4.w; a = fmaxf(a, 0.2f * a); e = __expf(a); den.w += e; num.w += e * y4.w;
    }
    float4 o;
    o.x = num.x / (den.x + 1e-16f);
    o.y = num.y / (den.y + 1e-16f);
    o.z = num.z / (den.z + 1e-16f);
    o.w = num.w / (den.w + 1e-16f);
    *reinterpret_cast<float4*>(out + (size_t)w * 128 + c) = o;
}

// ---------------- GRU ----------------
__global__ void gru_kernel(const float* __restrict__ state, const float* __restrict__ input_,
                           const float* __restrict__ W_in, const float* __restrict__ W_z,
                           const float* __restrict__ W_r, const float* __restrict__ W_h,
                           float* __restrict__ h_out, float* __restrict__ h_out2, int L)
{
    __shared__ float mi[128], inp[128], st[128], rs[128], zz[128];
    int b = blockIdx.x, t = threadIdx.x;
    const float* ib = input_ + (size_t)b * L * 128;
    float s = 0.f;
    for (int l = 0; l < L; l++) s += ib[l * 128 + t];
    mi[t] = s / (float)L;
    st[t] = state[b * 128 + t];
    __syncthreads();
    {
        float acc = 0.f;
        const float* wr = W_in + t * 128;
        for (int d = 0; d < 128; d++) acc += mi[d] * wr[d];
        inp[t] = acc;
    }
    __syncthreads();
    float az = 0.f, ar = 0.f;
    {
        const float* wz = W_z + t * 256;
        const float* wr = W_r + t * 256;
        for (int d = 0; d < 128; d++) { az += st[d] * wz[d];        ar += st[d] * wr[d]; }
        for (int d = 0; d < 128; d++) { az += inp[d] * wz[128 + d]; ar += inp[d] * wr[128 + d]; }
    }
    float z = 1.f / (1.f + expf(-az));
    float r = 1.f / (1.f + expf(-ar));
    zz[t] = z;
    rs[t] = r * st[t];
    __syncthreads();
    float ah = 0.f;
    {
        const float* wh = W_h + t * 256;
        for (int d = 0; d < 128; d++) ah += rs[d] * wh[d];
        for (int d = 0; d < 128; d++) ah += inp[d] * wh[128 + d];
    }
    float ht = tanhf(ah);
    float h = (1.f - zz[t]) * st[t] + zz[t] * ht;
    h_out[b * 128 + t] = h;
    h_out2[b * 128 + t] = h;
}

// ---------------- head: prob logits + sisr (one warp per node, float4 lanes) ----------------
__global__ void head_kernel(const float* __restrict__ feat, const float* __restrict__ h,
                            const float* __restrict__ Wp, const float* __restrict__ bp,
                            const float* __restrict__ Wsv, const float* __restrict__ bsv,
                            float* __restrict__ praw, float* __restrict__ sisr, int N, int NN)
{
    int w = (blockIdx.x * blockDim.x + threadIdx.x) >> 5;
    int lane = threadIdx.x & 31;
    if (w >= N) return;
    int b = w / NN;
    const int c = lane * 4;
    float4 f  = *reinterpret_cast<const float4*>(feat + (size_t)w * 128 + c);
    float4 hh = *reinterpret_cast<const float4*>(h + b * 128 + c);
    float4 wp = *reinterpret_cast<const float4*>(Wp + c);
    float4 ws = *reinterpret_cast<const float4*>(Wsv + c);
    float4 xg;
    xg.x = f.x * hh.x; xg.y = f.y * hh.y; xg.z = f.z * hh.z; xg.w = f.w * hh.w;
    float p = xg.x * wp.x + xg.y * wp.y + xg.z * wp.z + xg.w * wp.w;
    float s = xg.x * ws.x + xg.y * ws.y + xg.z * ws.z + xg.w * ws.w;
    for (int off = 16; off; off >>= 1) {
        p += __shfl_xor_sync(0xffffffffu, p, off);
        s += __shfl_xor_sync(0xffffffffu, s, off);
    }
    if (lane == 0) {
        praw[w] = p + bp[0];
        sisr[w] = 1.f / (1.f + expf(-(s + bsv[0])));
    }
}

// ---------------- softmax over prob[:, 1:] per batch ----------------
__global__ void softmax_kernel(const float* __restrict__ praw, float* __restrict__ prob, int NN)
{
    __shared__ float red[512];
    int b = blockIdx.x, t = threadIdx.x;
    int n = t + 1;
    float v = (n < NN) ? praw[b * NN + n] : -1e30f;
    red[t] = v; __syncthreads();
    for (int off = 256; off; off >>= 1) {
        if (t < off) red[t] = fmaxf(red[t], red[t + off]);
        __syncthreads();
    }
    float m = red[0];
    __syncthreads();
    float e = (n < NN) ? expf(v - m) : 0.f;
    red[t] = e; __syncthreads();
    for (int off = 256; off; off >>= 1) {
        if (t < off) red[t] = red[t] + red[t + off];
        __syncthreads();
    }
    float sum = red[0];
    if (n < NN) prob[b * (NN - 1) + t] = e / sum;
}

// ---------------- launch ----------------
extern "C" void kernel_launch(void* const* d_in, const int* in_sizes, int n_in,
                              void* d_out, int out_size)
{
    const float* x      = (const float*)d_in[0];
    const int*   e0     = (const int*)  d_in[1];
    const int*   e1     = (const int*)  d_in[2];
    const float* state  = (const float*)d_in[3];
    const float* input_ = (const float*)d_in[4];
    const float* W_in   = (const float*)d_in[5];
    const float* W_z    = (const float*)d_in[6];
    const float* W_r    = (const float*)d_in[7];
    const float* W_h    = (const float*)d_in[8];
    const float* Wlin[2] = { (const float*)d_in[9],  (const float*)d_in[13] };
    const float* blin[2] = { (const float*)d_in[10], (const float*)d_in[14] };
    const float* Wat [2] = { (const float*)d_in[11], (const float*)d_in[15] };
    const float* bat [2] = { (const float*)d_in[12], (const float*)d_in[16] };
    const float* Wp     = (const float*)d_in[17];
    const float* bp     = (const float*)d_in[18];
    const float* Wsv    = (const float*)d_in[19];
    const float* bsv    = (const float*)d_in[20];

    const int N    = in_sizes[0] / 128;
    const int E    = in_sizes[1] / 2;
    const int B    = in_sizes[3] / 128;
    const int L    = in_sizes[4] / (B * 128);
    const int NN   = N / B;
    const int Etot = E + N;

    float *yp, *aip, *ajp, *featp, *hp, *prawp;
    int *cntp, *rowp, *curp, *srcp, *auxp;
    __nv_bfloat16 *wlinH, *wlinL, *watH, *watL;
    cudaGetSymbolAddress((void**)&yp,    g_y);
    cudaGetSymbolAddress((void**)&aip,   g_ai);
    cudaGetSymbolAddress((void**)&ajp,   g_aj);
    cudaGetSymbolAddress((void**)&featp, g_feat);
    cudaGetSymbolAddress((void**)&hp,    g_h);
    cudaGetSymbolAddress((void**)&prawp, g_praw);
    cudaGetSymbolAddress((void**)&cntp,  g_cnt);
    cudaGetSymbolAddress((void**)&rowp,  g_rowptr);
    cudaGetSymbolAddress((void**)&curp,  g_cursor);
    cudaGetSymbolAddress((void**)&srcp,  g_srcs);
    cudaGetSymbolAddress((void**)&auxp,  g_aux);
    cudaGetSymbolAddress((void**)&wlinH, g_wlinH);
    cudaGetSymbolAddress((void**)&wlinL, g_wlinL);
    cudaGetSymbolAddress((void**)&watH,  g_watH);
    cudaGetSymbolAddress((void**)&watL,  g_watL);

    float* out      = (float*)d_out;
    float* out_prob = out;
    float* out_sisr = out + (size_t)B * (NN - 1);
    float* out_h    = out + (size_t)B * (NN - 1) + (size_t)B * NN;

    cudaFuncSetAttribute(gemm_wmma_kernel, cudaFuncAttributeMaxDynamicSharedMemorySize, GEMM_SMEM);

    const int nbScan = (N + 255) / 256;
    const int gHist  = (Etot + 255) / 256;
    const int gWarp  = (N * 32 + 255) / 256;
    const int gGemm  = (N + 63) / 64;

    gru_kernel<<<B, 128>>>(state, input_, W_in, W_z, W_r, W_h, hp, out_h, L);           // 1

    for (int layer = 0; layer < 2; layer++) {
        const int* ei = layer ? e1 : e0;           // [2, E]: row 0 = src, row 1 = dst
        const float* Ain = layer ? featp : x;

        prep_w_kernel<<<192, 256>>>(Wlin[layer], Wat[layer], wlinH, wlinL, watH, watL); // 2
        zero_kernel  <<<nbScan, 256>>>(cntp, N);                                        // 3

        // y = A@Wlin^T + blin   (4th launch overall -> ncu capture slot)
        gemm_wmma_kernel<<<gGemm, 256, GEMM_SMEM>>>(Ain, wlinH, wlinL, blin[layer],
                                                    yp, N);                             // 4

        hist_kernel   <<<gHist, 256>>>(ei + E, E, N, cntp);
        scan1_kernel  <<<nbScan, 256>>>(cntp, N, rowp, auxp);
        scan2_kernel  <<<1, 256>>>(auxp, nbScan, N, Etot, rowp);
        scan3_kernel  <<<nbScan, 256>>>(rowp, auxp, curp, N);
        scatter_kernel<<<gHist, 256>>>(ei, ei + E, E, N, curp, srcp);

        // attention: ai = y@Wi^T + b_attn ; aj = y@Wj^T
        gemm_wmma_kernel<<<gGemm, 256, GEMM_SMEM>>>(yp, watH, watL, bat[layer], aip, N);
        gemm_wmma_kernel<<<gGemm, 256, GEMM_SMEM>>>(yp, watH + 128 * 128, watL + 128 * 128,
                                                    (const float*)nullptr, ajp, N);

        edge_agg_kernel<<<gWarp, 256>>>(rowp, srcp, aip, ajp, yp, featp, N);
    }

    head_kernel   <<<gWarp, 256>>>(featp, hp, Wp, bp, Wsv, bsv, prawp, out_sisr, N, NN);
    softmax_kernel<<<B, 512>>>(prawp, out_prob, NN);
}